// round 5
// baseline (speedup 1.0000x reference)
#include <cuda_runtime.h>
#include <cuda_fp16.h>
#include <cstdint>
#include <math.h>

#define NTOK 8192
#define HDIM 1024
#define FDIM 4096
#define NEXP 8
#define NROWS (NTOK*2)

// ---------------- device scratch (allocation-free) ----------------
__device__ int    g_cnt[NEXP];
__device__ int    g_fill[NEXP];
__device__ int    g_off[NEXP+1];
__device__ int    g_tp[NEXP+1];
__device__ int    g_tok_e[NTOK*2];
__device__ float  g_tok_w[NTOK*2];
__device__ int    g_pos[NTOK*2];
__device__ int    g_row_token[NROWS];
__device__ __half g_hidden[(size_t)NROWS*FDIM];   // 134 MB grouped hidden (fp16)
__device__ __half g_xh[(size_t)NTOK*HDIM];        // x fp16
__device__ __half g_w1h[(size_t)NEXP*HDIM*FDIM];  // w1 fp16 [e][H][F]
__device__ __half g_w2h[(size_t)NEXP*FDIM*HDIM];  // w2 fp16 [e][F][H]
__device__ float  g_eout[(size_t)NROWS*HDIM];     // per-row GEMM2 out fp32

// ---------------- helpers ----------------
__device__ __forceinline__ uint32_t smem_u32(const void* p) {
    uint32_t a;
    asm("{ .reg .u64 t; cvta.to.shared.u64 t, %1; cvt.u32.u64 %0, t; }" : "=r"(a) : "l"(p));
    return a;
}
#define CPA16(dst,src,sz) asm volatile("cp.async.cg.shared.global [%0],[%1],16,%2;" :: "r"(dst), "l"(src), "r"(sz))
#define CPA_COMMIT() asm volatile("cp.async.commit_group;" ::: "memory")
#define CPA_WAIT2()  asm volatile("cp.async.wait_group 2;" ::: "memory")

__device__ __forceinline__ void ldsm_x4(uint32_t& r0, uint32_t& r1, uint32_t& r2, uint32_t& r3, uint32_t a) {
    asm volatile("ldmatrix.sync.aligned.m8n8.x4.shared.b16 {%0,%1,%2,%3},[%4];"
                 : "=r"(r0), "=r"(r1), "=r"(r2), "=r"(r3) : "r"(a));
}
__device__ __forceinline__ void ldsm_x4t(uint32_t& r0, uint32_t& r1, uint32_t& r2, uint32_t& r3, uint32_t a) {
    asm volatile("ldmatrix.sync.aligned.m8n8.x4.trans.shared.b16 {%0,%1,%2,%3},[%4];"
                 : "=r"(r0), "=r"(r1), "=r"(r2), "=r"(r3) : "r"(a));
}
__device__ __forceinline__ void mma16816(float* c, const uint32_t* a, const uint32_t* b) {
    asm volatile("mma.sync.aligned.m16n8k16.row.col.f32.f16.f16.f32 "
                 "{%0,%1,%2,%3},{%4,%5,%6,%7},{%8,%9},{%0,%1,%2,%3};"
                 : "+f"(c[0]), "+f"(c[1]), "+f"(c[2]), "+f"(c[3])
                 : "r"(a[0]), "r"(a[1]), "r"(a[2]), "r"(a[3]), "r"(b[0]), "r"(b[1]));
}
__device__ __forceinline__ float gelu_exact(float v) {
    return 0.5f * v * (1.f + erff(v * 0.70710678118654752f));
}

// ---------------- small kernels ----------------
__global__ void k_init() {
    int i = threadIdx.x;
    if (i < NEXP) { g_cnt[i] = 0; g_fill[i] = 0; }
}
// one grid-stride kernel converts x, w1, w2 to fp16
__global__ void k_convert_all(const float4* __restrict__ x,
                              const float4* __restrict__ w1,
                              const float4* __restrict__ w2,
                              uint2* __restrict__ xh,
                              uint2* __restrict__ w1h,
                              uint2* __restrict__ w2h) {
    const int NX = NTOK*HDIM/4, NW = NEXP*HDIM*FDIM/4;
    int total = NX + 2*NW;
    for (int i = blockIdx.x * blockDim.x + threadIdx.x; i < total; i += gridDim.x * blockDim.x) {
        const float4* s; uint2* d; int j;
        if (i < NW)            { s = w1; d = w1h; j = i; }
        else if (i < 2*NW)     { s = w2; d = w2h; j = i - NW; }
        else                   { s = x;  d = xh;  j = i - 2*NW; }
        float4 v = s[j];
        __half2 a = __floats2half2_rn(v.x, v.y);
        __half2 b = __floats2half2_rn(v.z, v.w);
        d[j] = make_uint2(*(uint32_t*)&a, *(uint32_t*)&b);
    }
}

__global__ void k_router(const float* __restrict__ x,
                         const float* __restrict__ rw,
                         const float* __restrict__ rb) {
    int warp = (blockIdx.x * blockDim.x + threadIdx.x) >> 5;
    int lane = threadIdx.x & 31;
    if (warp >= NTOK) return;
    const float* xr = x + (size_t)warp * HDIM;
    float acc[NEXP];
#pragma unroll
    for (int e = 0; e < NEXP; e++) acc[e] = 0.f;
    for (int h = lane; h < HDIM; h += 32) {
        float xv = __ldg(xr + h);
#pragma unroll
        for (int e = 0; e < NEXP; e++)
            acc[e] = fmaf(xv, __ldg(rw + e * HDIM + h), acc[e]);
    }
#pragma unroll
    for (int o = 16; o > 0; o >>= 1)
#pragma unroll
        for (int e = 0; e < NEXP; e++)
            acc[e] += __shfl_xor_sync(0xffffffffu, acc[e], o);
    if (lane == 0) {
        float l[NEXP];
#pragma unroll
        for (int e = 0; e < NEXP; e++) l[e] = acc[e] + rb[e];
        int i0 = 0; float b0 = l[0];
#pragma unroll
        for (int e = 1; e < NEXP; e++) if (l[e] > b0) { b0 = l[e]; i0 = e; }
        int i1 = (i0 == 0) ? 1 : 0; float b1 = -3.4e38f;
#pragma unroll
        for (int e = 0; e < NEXP; e++)
            if (e != i0 && l[e] > b1) { b1 = l[e]; i1 = e; }
        float w0 = 1.f / (1.f + expf(b1 - b0));
        g_tok_e[warp*2]   = i0;  g_tok_e[warp*2+1] = i1;
        g_tok_w[warp*2]   = w0;  g_tok_w[warp*2+1] = 1.f - w0;
        atomicAdd(&g_cnt[i0], 1);
        atomicAdd(&g_cnt[i1], 1);
    }
}
__global__ void k_offsets() {
    g_off[0] = 0; g_tp[0] = 0;
    for (int e = 0; e < NEXP; e++) {
        g_off[e+1] = g_off[e] + g_cnt[e];
        g_tp[e+1]  = g_tp[e]  + (g_cnt[e] + 127) / 128;
    }
}
__global__ void k_scatter() {
    int i = blockIdx.x * blockDim.x + threadIdx.x;
    if (i >= NTOK * 2) return;
    int e = g_tok_e[i];
    int r = g_off[e] + atomicAdd(&g_fill[e], 1);
    g_row_token[r] = i >> 1;
    g_pos[i] = r;
}
__global__ void k_combine(float* __restrict__ out) {
    int idx = blockIdx.x * blockDim.x + threadIdx.x;
    if (idx >= NTOK * HDIM / 4) return;
    int tok = idx / (HDIM / 4);
    int c4  = idx % (HDIM / 4);
    float w0 = g_tok_w[tok*2], w1 = g_tok_w[tok*2+1];
    int   r0 = g_pos[tok*2],  r1 = g_pos[tok*2+1];
    float4 a = ((const float4*)(g_eout + (size_t)r0 * HDIM))[c4];
    float4 b = ((const float4*)(g_eout + (size_t)r1 * HDIM))[c4];
    float4 o;
    o.x = w0 * a.x + w1 * b.x;  o.y = w0 * a.y + w1 * b.y;
    o.z = w0 * a.z + w1 * b.z;  o.w = w0 * a.w + w1 * b.w;
    ((float4*)out)[idx] = o;
}

// ---------------- grouped GEMM: 128x256x64 CTA tile, warp 64x64, 4-stage cp.async ----------------
#define BK 64
#define BN 256
#define LDA 72      // A row: 64 halfs + 8 pad (144B)
#define LDB 264     // B row: 256 halfs + 8 pad (528B)
#define STG_A (128*LDA*2)
#define STG_B (BK*LDB*2)
#define STG   (STG_A + STG_B)
#define SMEM_BYTES (4*STG)

// MODE 1: A = g_xh gathered by token, B = g_w1h -> GELU -> g_hidden (fp16)
// MODE 2: A = g_hidden grouped rows,  B = g_w2h -> g_eout (fp32)
template<int KDIM, int NDIM, int MODE>
__global__ void __launch_bounds__(256, 1)
k_gemm_cp(float* __restrict__ dummy)
{
    extern __shared__ char smem[];
    uint32_t sb = smem_u32(smem);

    const int colTiles = NDIM / BN;
    int totalRT = g_tp[NEXP];
    int t = blockIdx.x;
    if (t >= totalRT * colTiles) return;
    int rt = t % totalRT;
    int ct = t / totalRT;
    int e = 0;
    while (g_tp[e+1] <= rt) e++;
    int row0   = g_off[e] + (rt - g_tp[e]) * 128;
    int rowEnd = g_off[e+1];
    int n0 = ct * BN;

    const __half* Wh = ((MODE == 1) ? g_w1h : g_w2h) + (size_t)e * KDIM * NDIM;

    int tid = threadIdx.x, lane = tid & 31, wid = tid >> 5;
    int wm = wid >> 2, wn = wid & 3;   // 2 x 4 warps, each 64x64

    // ---- A loader: 2 threads/row, 64B each ----
    int lrowA = tid >> 1;
    int asub  = (tid & 1) * 32;
    int gr = row0 + lrowA;
    bool av = (gr < rowEnd);
    const __half* asrc;
    if (MODE == 1) asrc = g_xh     + (size_t)(av ? g_row_token[gr] : 0) * KDIM + asub;
    else           asrc = g_hidden + (size_t)(av ? gr : 0) * KDIM + asub;
    int asz = av ? 16 : 0;

    // ---- B loader: 4 threads/row, 128B each ----
    int lrowB = tid >> 2;
    int bsub  = (tid & 3) * 64;
    const __half* bsrc = Wh + (size_t)lrowB * NDIM + n0 + bsub;

    uint32_t aDst[4], bDst[8];
#pragma unroll
    for (int i = 0; i < 4; i++)
        aDst[i] = sb + (uint32_t)((lrowA * LDA + asub + i * 8) * 2);
#pragma unroll
    for (int i = 0; i < 8; i++)
        bDst[i] = sb + STG_A + (uint32_t)((lrowB * LDB + bsub + i * 8) * 2);

    float acc[4][8][4];
#pragma unroll
    for (int mi = 0; mi < 4; mi++)
#pragma unroll
        for (int ni = 0; ni < 8; ni++)
#pragma unroll
            for (int k = 0; k < 4; k++) acc[mi][ni][k] = 0.f;

    const int NKB = KDIM / BK;

#define ISSUE(c) do { \
        uint32_t so = ((c) & 3) * STG; \
        const __half* as_ = asrc + (c) * BK; \
        const __half* bs_ = bsrc + (size_t)(c) * BK * NDIM; \
        _Pragma("unroll") \
        for (int i_ = 0; i_ < 4; i_++) CPA16(aDst[i_] + so, as_ + i_ * 8, asz); \
        _Pragma("unroll") \
        for (int i_ = 0; i_ < 8; i_++) CPA16(bDst[i_] + so, bs_ + (size_t)i_ * 8, 16); \
    } while(0)

    ISSUE(0); CPA_COMMIT();
    ISSUE(1); CPA_COMMIT();
    ISSUE(2); CPA_COMMIT();

    for (int kb = 0; kb < NKB; kb++) {
        CPA_WAIT2();
        __syncthreads();
        if (kb + 3 < NKB) ISSUE(kb + 3);
        CPA_COMMIT();

        uint32_t abase = sb + (kb & 3) * STG;
        uint32_t bbase = abase + STG_A;
#pragma unroll
        for (int kk = 0; kk < 4; kk++) {
            int k0 = kk * 16;
            uint32_t afr[4][4];
#pragma unroll
            for (int mi = 0; mi < 4; mi++) {
                uint32_t addr = abase + (uint32_t)(((wm * 64 + mi * 16 + (lane & 15)) * LDA
                                                    + k0 + (lane >> 4) * 8) * 2);
                ldsm_x4(afr[mi][0], afr[mi][1], afr[mi][2], afr[mi][3], addr);
            }
            uint32_t bfr[8][2];
#pragma unroll
            for (int nb = 0; nb < 4; nb++) {
                uint32_t addr = bbase + (uint32_t)(((k0 + (lane & 15)) * LDB
                                                    + wn * 64 + nb * 16 + (lane >> 4) * 8) * 2);
                uint32_t r0, r1, r2, r3;
                ldsm_x4t(r0, r1, r2, r3, addr);
                bfr[nb*2][0] = r0;   bfr[nb*2][1] = r1;
                bfr[nb*2+1][0] = r2; bfr[nb*2+1][1] = r3;
            }
#pragma unroll
            for (int mi = 0; mi < 4; mi++)
#pragma unroll
                for (int ni = 0; ni < 8; ni++)
                    mma16816(acc[mi][ni], afr[mi], bfr[ni]);
        }
        __syncthreads();
    }
#undef ISSUE

    // ---- epilogue ----
    int mrow = row0 + wm * 64 + (lane >> 2);
    int ncol = n0 + wn * 64 + (lane & 3) * 2;
#pragma unroll
    for (int mi = 0; mi < 4; mi++) {
#pragma unroll
        for (int ni = 0; ni < 8; ni++) {
            int r0r = mrow + mi * 16;
            int c   = ncol + ni * 8;
            if (MODE == 1) {
                if (r0r < rowEnd) {
                    __half2 h = __floats2half2_rn(gelu_exact(acc[mi][ni][0]),
                                                  gelu_exact(acc[mi][ni][1]));
                    *(__half2*)&g_hidden[(size_t)r0r * NDIM + c] = h;
                }
                if (r0r + 8 < rowEnd) {
                    __half2 h = __floats2half2_rn(gelu_exact(acc[mi][ni][2]),
                                                  gelu_exact(acc[mi][ni][3]));
                    *(__half2*)&g_hidden[(size_t)(r0r + 8) * NDIM + c] = h;
                }
            } else {
                if (r0r < rowEnd)
                    *(float2*)&g_eout[(size_t)r0r * NDIM + c] =
                        make_float2(acc[mi][ni][0], acc[mi][ni][1]);
                if (r0r + 8 < rowEnd)
                    *(float2*)&g_eout[(size_t)(r0r + 8) * NDIM + c] =
                        make_float2(acc[mi][ni][2], acc[mi][ni][3]);
            }
        }
    }
}

// ---------------- launch ----------------
extern "C" void kernel_launch(void* const* d_in, const int* in_sizes, int n_in,
                              void* d_out, int out_size) {
    const float* x  = (const float*)d_in[0];
    const float* rw = (const float*)d_in[1];
    const float* rb = (const float*)d_in[2];
    const float* w1 = (const float*)d_in[3];
    const float* w2 = (const float*)d_in[4];
    float* out = (float*)d_out;

    static bool attr_set = false;
    if (!attr_set) {
        cudaFuncSetAttribute((const void*)k_gemm_cp<HDIM, FDIM, 1>,
                             cudaFuncAttributeMaxDynamicSharedMemorySize, SMEM_BYTES);
        cudaFuncSetAttribute((const void*)k_gemm_cp<FDIM, HDIM, 2>,
                             cudaFuncAttributeMaxDynamicSharedMemorySize, SMEM_BYTES);
        attr_set = true;
    }

    k_init<<<1, 32>>>();
    {
        __half *xh_p, *w1h_p, *w2h_p;
        cudaGetSymbolAddress((void**)&xh_p,  g_xh);
        cudaGetSymbolAddress((void**)&w1h_p, g_w1h);
        cudaGetSymbolAddress((void**)&w2h_p, g_w2h);
        k_convert_all<<<2048, 256>>>((const float4*)x, (const float4*)w1, (const float4*)w2,
                                     (uint2*)xh_p, (uint2*)w1h_p, (uint2*)w2h_p);
    }
    k_router<<<NTOK/8, 256>>>(x, rw, rb);
    k_offsets<<<1, 1>>>();
    k_scatter<<<(NTOK*2 + 255)/256, 256>>>();

    k_gemm_cp<HDIM, FDIM, 1><<<136*(FDIM/BN), 256, SMEM_BYTES>>>(nullptr);
    k_gemm_cp<FDIM, HDIM, 2><<<136*(HDIM/BN), 256, SMEM_BYTES>>>(nullptr);

    k_combine<<<(NTOK*HDIM/4 + 255)/256, 256>>>(out);
}

// round 6
// speedup vs baseline: 1.1638x; 1.1638x over previous
#include <cuda_runtime.h>
#include <cuda_fp16.h>
#include <cstdint>
#include <math.h>

#define NTOK 8192
#define HDIM 1024
#define FDIM 4096
#define NEXP 8
#define NROWS (NTOK*2)

// ---------------- device scratch (allocation-free) ----------------
__device__ int    g_cnt[NEXP];
__device__ int    g_fill[NEXP];
__device__ int    g_off[NEXP+1];
__device__ int    g_tp[NEXP+1];
__device__ int    g_tok_e[NTOK*2];
__device__ float  g_tok_w[NTOK*2];
__device__ int    g_pos[NTOK*2];
__device__ int    g_row_token[NROWS];
__device__ __half g_hidden[(size_t)NROWS*FDIM];   // 134 MB grouped hidden (fp16)
__device__ __half g_xh[(size_t)NTOK*HDIM];        // x fp16
__device__ __half g_w1h[(size_t)NEXP*HDIM*FDIM];  // w1 fp16 [e][H][F]
__device__ __half g_w2h[(size_t)NEXP*FDIM*HDIM];  // w2 fp16 [e][F][H]
__device__ float  g_eout[(size_t)NROWS*HDIM];     // per-row GEMM2 out fp32

// ---------------- helpers ----------------
__device__ __forceinline__ uint32_t smem_u32(const void* p) {
    uint32_t a;
    asm("{ .reg .u64 t; cvta.to.shared.u64 t, %1; cvt.u32.u64 %0, t; }" : "=r"(a) : "l"(p));
    return a;
}
#define CPA16(dst,src,sz) asm volatile("cp.async.cg.shared.global [%0],[%1],16,%2;" :: "r"(dst), "l"(src), "r"(sz))
#define CPA_COMMIT() asm volatile("cp.async.commit_group;" ::: "memory")
#define CPA_WAIT1()  asm volatile("cp.async.wait_group 1;" ::: "memory")

__device__ __forceinline__ void ldsm_x4(uint32_t& r0, uint32_t& r1, uint32_t& r2, uint32_t& r3, uint32_t a) {
    asm volatile("ldmatrix.sync.aligned.m8n8.x4.shared.b16 {%0,%1,%2,%3},[%4];"
                 : "=r"(r0), "=r"(r1), "=r"(r2), "=r"(r3) : "r"(a));
}
__device__ __forceinline__ void ldsm_x4t(uint32_t& r0, uint32_t& r1, uint32_t& r2, uint32_t& r3, uint32_t a) {
    asm volatile("ldmatrix.sync.aligned.m8n8.x4.trans.shared.b16 {%0,%1,%2,%3},[%4];"
                 : "=r"(r0), "=r"(r1), "=r"(r2), "=r"(r3) : "r"(a));
}
__device__ __forceinline__ void mma16816(float* c, const uint32_t* a, const uint32_t* b) {
    asm volatile("mma.sync.aligned.m16n8k16.row.col.f32.f16.f16.f32 "
                 "{%0,%1,%2,%3},{%4,%5,%6,%7},{%8,%9},{%0,%1,%2,%3};"
                 : "+f"(c[0]), "+f"(c[1]), "+f"(c[2]), "+f"(c[3])
                 : "r"(a[0]), "r"(a[1]), "r"(a[2]), "r"(a[3]), "r"(b[0]), "r"(b[1]));
}
__device__ __forceinline__ float gelu_exact(float v) {
    return 0.5f * v * (1.f + erff(v * 0.70710678118654752f));
}

// ---------------- small kernels ----------------
// converts x, w1, w2 to fp16; block 0 also zeroes the routing counters
__global__ void k_convert_all(const float4* __restrict__ x,
                              const float4* __restrict__ w1,
                              const float4* __restrict__ w2,
                              uint2* __restrict__ xh,
                              uint2* __restrict__ w1h,
                              uint2* __restrict__ w2h) {
    if (blockIdx.x == 0 && threadIdx.x < NEXP) {
        g_cnt[threadIdx.x] = 0; g_fill[threadIdx.x] = 0;
    }
    const int NX = NTOK*HDIM/4, NW = NEXP*HDIM*FDIM/4;
    int total = NX + 2*NW;
    for (int i = blockIdx.x * blockDim.x + threadIdx.x; i < total; i += gridDim.x * blockDim.x) {
        const float4* s; uint2* d; int j;
        if (i < NW)            { s = w1; d = w1h; j = i; }
        else if (i < 2*NW)     { s = w2; d = w2h; j = i - NW; }
        else                   { s = x;  d = xh;  j = i - 2*NW; }
        float4 v = s[j];
        __half2 a = __floats2half2_rn(v.x, v.y);
        __half2 b = __floats2half2_rn(v.z, v.w);
        d[j] = make_uint2(*(uint32_t*)&a, *(uint32_t*)&b);
    }
}

__global__ void k_router(const float* __restrict__ x,
                         const float* __restrict__ rw,
                         const float* __restrict__ rb) {
    int warp = (blockIdx.x * blockDim.x + threadIdx.x) >> 5;
    int lane = threadIdx.x & 31;
    if (warp >= NTOK) return;
    const float* xr = x + (size_t)warp * HDIM;
    float acc[NEXP];
#pragma unroll
    for (int e = 0; e < NEXP; e++) acc[e] = 0.f;
    for (int h = lane; h < HDIM; h += 32) {
        float xv = __ldg(xr + h);
#pragma unroll
        for (int e = 0; e < NEXP; e++)
            acc[e] = fmaf(xv, __ldg(rw + e * HDIM + h), acc[e]);
    }
#pragma unroll
    for (int o = 16; o > 0; o >>= 1)
#pragma unroll
        for (int e = 0; e < NEXP; e++)
            acc[e] += __shfl_xor_sync(0xffffffffu, acc[e], o);
    if (lane == 0) {
        float l[NEXP];
#pragma unroll
        for (int e = 0; e < NEXP; e++) l[e] = acc[e] + rb[e];
        int i0 = 0; float b0 = l[0];
#pragma unroll
        for (int e = 1; e < NEXP; e++) if (l[e] > b0) { b0 = l[e]; i0 = e; }
        int i1 = (i0 == 0) ? 1 : 0; float b1 = -3.4e38f;
#pragma unroll
        for (int e = 0; e < NEXP; e++)
            if (e != i0 && l[e] > b1) { b1 = l[e]; i1 = e; }
        float w0 = 1.f / (1.f + expf(b1 - b0));
        g_tok_e[warp*2]   = i0;  g_tok_e[warp*2+1] = i1;
        g_tok_w[warp*2]   = w0;  g_tok_w[warp*2+1] = 1.f - w0;
        atomicAdd(&g_cnt[i0], 1);
        atomicAdd(&g_cnt[i1], 1);
    }
}
__global__ void k_offsets() {
    g_off[0] = 0; g_tp[0] = 0;
    for (int e = 0; e < NEXP; e++) {
        g_off[e+1] = g_off[e] + g_cnt[e];
        g_tp[e+1]  = g_tp[e]  + (g_cnt[e] + 127) / 128;
    }
}
__global__ void k_scatter() {
    int i = blockIdx.x * blockDim.x + threadIdx.x;
    if (i >= NTOK * 2) return;
    int e = g_tok_e[i];
    int r = g_off[e] + atomicAdd(&g_fill[e], 1);
    g_row_token[r] = i >> 1;
    g_pos[i] = r;
}
__global__ void k_combine(float* __restrict__ out) {
    int idx = blockIdx.x * blockDim.x + threadIdx.x;
    if (idx >= NTOK * HDIM / 4) return;
    int tok = idx / (HDIM / 4);
    int c4  = idx % (HDIM / 4);
    float w0 = g_tok_w[tok*2], w1 = g_tok_w[tok*2+1];
    int   r0 = g_pos[tok*2],  r1 = g_pos[tok*2+1];
    float4 a = ((const float4*)(g_eout + (size_t)r0 * HDIM))[c4];
    float4 b = ((const float4*)(g_eout + (size_t)r1 * HDIM))[c4];
    float4 o;
    o.x = w0 * a.x + w1 * b.x;  o.y = w0 * a.y + w1 * b.y;
    o.z = w0 * a.z + w1 * b.z;  o.w = w0 * a.w + w1 * b.w;
    ((float4*)out)[idx] = o;
}

// ---------------- grouped GEMM: 128x128x64, 3-stage cp.async, mma.sync fp16 ----------------
#define BK 64
#define LDA 72      // A smem row: 64 halfs + 8 pad (144B)
#define LDB 136     // B smem row: 128 halfs + 8 pad (272B)
#define STG_A (128*LDA*2)
#define STG_B (BK*LDB*2)
#define STG   (STG_A + STG_B)
#define SMEM_BYTES (3*STG)

// MODE 1: A = g_xh gathered by token, B = g_w1h -> GELU -> g_hidden (fp16)
// MODE 2: A = g_hidden grouped rows,  B = g_w2h -> g_eout (fp32)
template<int KDIM, int NDIM, int MODE>
__global__ void __launch_bounds__(256, 2)
k_gemm_cp(float* __restrict__ dummy)
{
    extern __shared__ char smem[];
    uint32_t sb = smem_u32(smem);

    const int colTiles = NDIM / 128;
    int totalRT = g_tp[NEXP];
    int t = blockIdx.x;
    if (t >= totalRT * colTiles) return;
    int rt = t % totalRT;
    int ct = t / totalRT;
    int e = 0;
    while (g_tp[e+1] <= rt) e++;
    int row0   = g_off[e] + (rt - g_tp[e]) * 128;
    int rowEnd = g_off[e+1];
    int n0 = ct * 128;

    const __half* Wh = ((MODE == 1) ? g_w1h : g_w2h) + (size_t)e * KDIM * NDIM;

    int tid = threadIdx.x, lane = tid & 31, wid = tid >> 5;
    int wm = wid >> 2, wn = wid & 3;

    // ---- A loader: 2 threads/row, 64B each ----
    int lrowA = tid >> 1;
    int asub  = (tid & 1) * 32;
    int gr = row0 + lrowA;
    bool av = (gr < rowEnd);
    const __half* asrc;
    if (MODE == 1) asrc = g_xh     + (size_t)(av ? g_row_token[gr] : 0) * KDIM + asub;
    else           asrc = g_hidden + (size_t)(av ? gr : 0) * KDIM + asub;
    int asz = av ? 16 : 0;

    // ---- B loader: 4 threads/row, 64B each ----
    int lrowB = tid >> 2;
    int bsub  = (tid & 3) * 32;
    const __half* bsrc = Wh + (size_t)lrowB * NDIM + n0 + bsub;

    uint32_t aDst[4], bDst[4];
#pragma unroll
    for (int i = 0; i < 4; i++) {
        aDst[i] = sb + (uint32_t)((lrowA * LDA + asub + i * 8) * 2);
        bDst[i] = sb + STG_A + (uint32_t)((lrowB * LDB + bsub + i * 8) * 2);
    }

    float acc[4][4][4];
#pragma unroll
    for (int mi = 0; mi < 4; mi++)
#pragma unroll
        for (int ni = 0; ni < 4; ni++)
#pragma unroll
            for (int k = 0; k < 4; k++) acc[mi][ni][k] = 0.f;

    const int NKB = KDIM / BK;

#define ISSUE(c) do { \
        uint32_t so = ((c) % 3) * STG; \
        const __half* as_ = asrc + (c) * BK; \
        const __half* bs_ = bsrc + (size_t)(c) * BK * NDIM; \
        _Pragma("unroll") \
        for (int i_ = 0; i_ < 4; i_++) CPA16(aDst[i_] + so, as_ + i_ * 8, asz); \
        _Pragma("unroll") \
        for (int i_ = 0; i_ < 4; i_++) CPA16(bDst[i_] + so, bs_ + (size_t)i_ * 8, 16); \
    } while(0)

    // preload stages 0,1 (one commit group each)
    ISSUE(0); CPA_COMMIT();
    ISSUE(1); CPA_COMMIT();

    for (int kb = 0; kb < NKB; kb++) {
        CPA_WAIT1();          // group kb fully resident
        __syncthreads();      // all warps past stage (kb-1) reads
        if (kb + 2 < NKB) ISSUE(kb + 2);   // writes stage (kb+2)%3 == (kb-1)%3, now safe
        CPA_COMMIT();         // exactly one group per iteration keeps accounting exact

        uint32_t abase = sb + (kb % 3) * STG;
        uint32_t bbase = abase + STG_A;
#pragma unroll
        for (int kk = 0; kk < 4; kk++) {
            int k0 = kk * 16;
            uint32_t afr[4][4];
#pragma unroll
            for (int mi = 0; mi < 4; mi++) {
                uint32_t addr = abase + (uint32_t)(((wm * 64 + mi * 16 + (lane & 15)) * LDA
                                                    + k0 + (lane >> 4) * 8) * 2);
                ldsm_x4(afr[mi][0], afr[mi][1], afr[mi][2], afr[mi][3], addr);
            }
            uint32_t bfr[4][2];
#pragma unroll
            for (int nb = 0; nb < 2; nb++) {
                uint32_t addr = bbase + (uint32_t)(((k0 + (lane & 15)) * LDB
                                                    + wn * 32 + nb * 16 + (lane >> 4) * 8) * 2);
                uint32_t r0, r1, r2, r3;
                ldsm_x4t(r0, r1, r2, r3, addr);
                bfr[nb*2][0] = r0;   bfr[nb*2][1] = r1;
                bfr[nb*2+1][0] = r2; bfr[nb*2+1][1] = r3;
            }
#pragma unroll
            for (int mi = 0; mi < 4; mi++)
#pragma unroll
                for (int ni = 0; ni < 4; ni++)
                    mma16816(acc[mi][ni], afr[mi], bfr[ni]);
        }
        // no bottom barrier: next iteration's top sync protects stage reuse
    }
#undef ISSUE

    // ---- epilogue ----
    int mrow = row0 + wm * 64 + (lane >> 2);
    int ncol = n0 + wn * 32 + (lane & 3) * 2;
#pragma unroll
    for (int mi = 0; mi < 4; mi++) {
#pragma unroll
        for (int ni = 0; ni < 4; ni++) {
            int r0r = mrow + mi * 16;
            int c   = ncol + ni * 8;
            if (MODE == 1) {
                if (r0r < rowEnd) {
                    __half2 h = __floats2half2_rn(gelu_exact(acc[mi][ni][0]),
                                                  gelu_exact(acc[mi][ni][1]));
                    *(__half2*)&g_hidden[(size_t)r0r * NDIM + c] = h;
                }
                if (r0r + 8 < rowEnd) {
                    __half2 h = __floats2half2_rn(gelu_exact(acc[mi][ni][2]),
                                                  gelu_exact(acc[mi][ni][3]));
                    *(__half2*)&g_hidden[(size_t)(r0r + 8) * NDIM + c] = h;
                }
            } else {
                if (r0r < rowEnd)
                    *(float2*)&g_eout[(size_t)r0r * NDIM + c] =
                        make_float2(acc[mi][ni][0], acc[mi][ni][1]);
                if (r0r + 8 < rowEnd)
                    *(float2*)&g_eout[(size_t)(r0r + 8) * NDIM + c] =
                        make_float2(acc[mi][ni][2], acc[mi][ni][3]);
            }
        }
    }
}

// ---------------- launch ----------------
extern "C" void kernel_launch(void* const* d_in, const int* in_sizes, int n_in,
                              void* d_out, int out_size) {
    const float* x  = (const float*)d_in[0];
    const float* rw = (const float*)d_in[1];
    const float* rb = (const float*)d_in[2];
    const float* w1 = (const float*)d_in[3];
    const float* w2 = (const float*)d_in[4];
    float* out = (float*)d_out;

    static bool attr_set = false;
    if (!attr_set) {
        cudaFuncSetAttribute((const void*)k_gemm_cp<HDIM, FDIM, 1>,
                             cudaFuncAttributeMaxDynamicSharedMemorySize, SMEM_BYTES);
        cudaFuncSetAttribute((const void*)k_gemm_cp<FDIM, HDIM, 2>,
                             cudaFuncAttributeMaxDynamicSharedMemorySize, SMEM_BYTES);
        attr_set = true;
    }

    {
        __half *xh_p, *w1h_p, *w2h_p;
        cudaGetSymbolAddress((void**)&xh_p,  g_xh);
        cudaGetSymbolAddress((void**)&w1h_p, g_w1h);
        cudaGetSymbolAddress((void**)&w2h_p, g_w2h);
        k_convert_all<<<2048, 256>>>((const float4*)x, (const float4*)w1, (const float4*)w2,
                                     (uint2*)xh_p, (uint2*)w1h_p, (uint2*)w2h_p);
    }
    k_router<<<NTOK/8, 256>>>(x, rw, rb);
    k_offsets<<<1, 1>>>();
    k_scatter<<<(NTOK*2 + 255)/256, 256>>>();

    k_gemm_cp<HDIM, FDIM, 1><<<136*32, 256, SMEM_BYTES>>>(nullptr);
    k_gemm_cp<FDIM, HDIM, 2><<<136*8, 256, SMEM_BYTES>>>(nullptr);

    k_combine<<<(NTOK*HDIM/4 + 255)/256, 256>>>(out);
}